// round 1
// baseline (speedup 1.0000x reference)
#include <cuda_runtime.h>
#include <math.h>
#include <stdint.h>

// Problem constants
#define BSZ  16384
#define HD   256
#define GXD  70
#define GYD  70
#define SWIN 2
#define NKW  25   // 5x5 window

// ---------------- scratch (static device memory, no allocations) ----------------
__device__ float g_xf  [(size_t)BSZ * 256];   // packed feature (stride 256)
__device__ float g_gi  [(size_t)BSZ * 1024];  // feat @ w_ih^T + b_ih
__device__ float g_gh  [(size_t)BSZ * 1024];  // hidden @ w_hh^T + b_hh
__device__ float g_comb[(size_t)BSZ * 512];   // [mix | q]
__device__ float g_sg  [(size_t)BSZ * 256];   // spatialgate
__device__ float g_ug  [(size_t)BSZ * 256];   // updategate

__device__ __forceinline__ float sigmoidf_(float x) {
    return 1.0f / (1.0f + expf(-x));
}

// ---------------- kernel 1: strip stride-258 input to stride-256 ----------------
__global__ __launch_bounds__(256) void pack_kernel(const float* __restrict__ in) {
    // BSZ*128 float2 elements, exactly 8192 blocks * 256 threads
    size_t i  = (size_t)blockIdx.x * blockDim.x + threadIdx.x;
    size_t b  = i >> 7;            // row
    int    c2 = (int)(i & 127);    // float2 column
    float2 v = *(const float2*)(in + b * 258 + 2 * c2);
    ((float2*)g_xf)[i] = v;
}

// ---------------- shared SGEMM core: C(MxN) = A(MxK,row) * W(NxK,row)^T ----------
// BM=BN=128, BK=16, 256 threads, 8x8 microtile, double-buffered smem.
template <int KD>
__device__ __forceinline__ void sgemm_body(const float* __restrict__ A,
                                           const float* __restrict__ W,
                                           float (&acc)[8][8]) {
    __shared__ float As[2][16][128];
    __shared__ float Bs[2][16][128];
    const int tid  = threadIdx.x;
    const int lrow = tid >> 1;          // 0..127
    const int lcol = (tid & 1) << 3;    // 0 or 8
    const float* Ap = A + (size_t)(blockIdx.y * 128 + lrow) * KD + lcol;
    const float* Wp = W + (size_t)(blockIdx.x * 128 + lrow) * KD + lcol;
    const int tx = tid & 15;            // N microtile
    const int ty = tid >> 4;            // M microtile

    auto load_tile = [&](int k0, int buf) {
        float4 a0 = *(const float4*)(Ap + k0);
        float4 a1 = *(const float4*)(Ap + k0 + 4);
        float4 w0 = *(const float4*)(Wp + k0);
        float4 w1 = *(const float4*)(Wp + k0 + 4);
        As[buf][lcol + 0][lrow] = a0.x; As[buf][lcol + 1][lrow] = a0.y;
        As[buf][lcol + 2][lrow] = a0.z; As[buf][lcol + 3][lrow] = a0.w;
        As[buf][lcol + 4][lrow] = a1.x; As[buf][lcol + 5][lrow] = a1.y;
        As[buf][lcol + 6][lrow] = a1.z; As[buf][lcol + 7][lrow] = a1.w;
        Bs[buf][lcol + 0][lrow] = w0.x; Bs[buf][lcol + 1][lrow] = w0.y;
        Bs[buf][lcol + 2][lrow] = w0.z; Bs[buf][lcol + 3][lrow] = w0.w;
        Bs[buf][lcol + 4][lrow] = w1.x; Bs[buf][lcol + 5][lrow] = w1.y;
        Bs[buf][lcol + 6][lrow] = w1.z; Bs[buf][lcol + 7][lrow] = w1.w;
    };

    load_tile(0, 0);
    __syncthreads();
    constexpr int NT = KD / 16;
#pragma unroll 2
    for (int t = 0; t < NT; t++) {
        const int buf = t & 1;
        if (t + 1 < NT) load_tile((t + 1) * 16, (t + 1) & 1);
#pragma unroll
        for (int k = 0; k < 16; k++) {
            float4 a0 = *(const float4*)&As[buf][k][ty * 8];
            float4 a1 = *(const float4*)&As[buf][k][ty * 8 + 4];
            float4 b0 = *(const float4*)&Bs[buf][k][tx * 8];
            float4 b1 = *(const float4*)&Bs[buf][k][tx * 8 + 4];
            float av[8] = {a0.x, a0.y, a0.z, a0.w, a1.x, a1.y, a1.z, a1.w};
            float bv[8] = {b0.x, b0.y, b0.z, b0.w, b1.x, b1.y, b1.z, b1.w};
#pragma unroll
            for (int i = 0; i < 8; i++)
#pragma unroll
                for (int j = 0; j < 8; j++)
                    acc[i][j] = fmaf(av[i], bv[j], acc[i][j]);
        }
        __syncthreads();
    }
}

// ---------------- kernel 2: gi / gh GEMMs (z=0: feature, z=1: hidden) -----------
__global__ __launch_bounds__(256, 2) void gemm1_kernel(
    const float* __restrict__ hidden,
    const float* __restrict__ w_ih, const float* __restrict__ b_ih,
    const float* __restrict__ w_hh, const float* __restrict__ b_hh) {
    const float* A; const float* W; const float* bias; float* C;
    if (blockIdx.z == 0) { A = g_xf;   W = w_ih; bias = b_ih; C = g_gi; }
    else                 { A = hidden; W = w_hh; bias = b_hh; C = g_gh; }

    float acc[8][8];
#pragma unroll
    for (int i = 0; i < 8; i++)
#pragma unroll
        for (int j = 0; j < 8; j++) acc[i][j] = 0.0f;

    sgemm_body<256>(A, W, acc);

    const int tx = threadIdx.x & 15, ty = threadIdx.x >> 4;
    const int r0 = blockIdx.y * 128 + ty * 8;
    const int c0 = blockIdx.x * 128 + tx * 8;
#pragma unroll
    for (int i = 0; i < 8; i++) {
        size_t ro = (size_t)(r0 + i) * 1024 + c0;
#pragma unroll
        for (int j = 0; j < 8; j += 4) {
            float4 v;
            v.x = acc[i][j + 0] + bias[c0 + j + 0];
            v.y = acc[i][j + 1] + bias[c0 + j + 1];
            v.z = acc[i][j + 2] + bias[c0 + j + 2];
            v.w = acc[i][j + 3] + bias[c0 + j + 3];
            *(float4*)(C + ro + j) = v;
        }
    }
}

// ---------------- kernel 3: gates + attention over 5x5 context ------------------
__global__ __launch_bounds__(256) void phaseB_kernel(
    const float* __restrict__ input_tensor,
    const float* __restrict__ memory) {
    const int b = blockIdx.x;
    const int t = threadIdx.x;

    __shared__ float q_s[HD];
    __shared__ float ctx[NKW][HD];
    __shared__ float attn_s[NKW];
    __shared__ float w_s[NKW];

    const float* gi = g_gi + (size_t)b * 1024;
    const float* gh = g_gh + (size_t)b * 1024;
    float i_r = gi[t],       h_r = gh[t];
    float i_i = gi[256 + t], h_i = gh[256 + t];
    float i_n = gi[512 + t], h_n = gh[512 + t];
    float i_s = gi[768 + t], h_s = gh[768 + t];

    float rg = sigmoidf_(i_r + h_r);
    float ug = sigmoidf_(i_i + h_i);
    float sg = sigmoidf_(i_s + h_s);
    float q  = tanhf(i_n + rg * h_n);
    q_s[t] = q;
    g_sg[(size_t)b * HD + t] = sg;
    g_ug[(size_t)b * HD + t] = ug;

    // grid coords: int cast + SW, clipped
    int gx = (int)input_tensor[(size_t)b * 258 + 256] + SWIN;
    int gy = (int)input_tensor[(size_t)b * 258 + 257] + SWIN;
    gx = min(max(gx, 0), GXD - 1);
    gy = min(max(gy, 0), GYD - 1);

    // gather 25 context rows into smem (coalesced over t)
#pragma unroll
    for (int k = 0; k < NKW; k++) {
        int xi = min(max(gx + k / 5 - SWIN, 0), GXD - 1);
        int yi = min(max(gy + k % 5 - SWIN, 0), GYD - 1);
        ctx[k][t] = __ldg(&memory[((size_t)xi * GYD + yi) * HD + t]);
    }
    __syncthreads();

    // attn_k = dot(q, ctx[k]); warp w handles k = w, w+8, w+16, w+24
    const int lane = t & 31, wrp = t >> 5;
    for (int k = wrp; k < NKW; k += 8) {
        float sum = 0.0f;
#pragma unroll
        for (int e = 0; e < 8; e++)
            sum += q_s[lane + e * 32] * ctx[k][lane + e * 32];
#pragma unroll
        for (int off = 16; off; off >>= 1)
            sum += __shfl_xor_sync(0xffffffffu, sum, off);
        if (lane == 0) attn_s[k] = sum;
    }
    __syncthreads();

    // softmax over 25 (one warp), with attn==0 -> -inf and NaN -> 0 semantics
    if (t < 32) {
        float v = (lane < NKW) ? attn_s[lane] : -INFINITY;
        if (v == 0.0f) v = -INFINITY;
        float mx = v;
#pragma unroll
        for (int off = 16; off; off >>= 1)
            mx = fmaxf(mx, __shfl_xor_sync(0xffffffffu, mx, off));
        float e = (mx == -INFINITY) ? 0.0f : expf(v - mx);
        float den = e;
#pragma unroll
        for (int off = 16; off; off >>= 1)
            den += __shfl_xor_sync(0xffffffffu, den, off);
        float wv = (den > 0.0f) ? (e / den) : 0.0f;
        if (lane < NKW) w_s[lane] = wv;
    }
    __syncthreads();

    // mix = sum_k w_k * ctx[k][:]
    float mix = 0.0f;
#pragma unroll
    for (int k = 0; k < NKW; k++)
        mix = fmaf(w_s[k], ctx[k][t], mix);

    g_comb[(size_t)b * 512 + t]       = mix;
    g_comb[(size_t)b * 512 + 256 + t] = q;
}

// ---------------- kernel 4: output GEMM + fused GRU epilogue --------------------
__global__ __launch_bounds__(256, 2) void gemm2_kernel(
    const float* __restrict__ w_out, const float* __restrict__ b_out,
    const float* __restrict__ hidden, float* __restrict__ out) {
    float acc[8][8];
#pragma unroll
    for (int i = 0; i < 8; i++)
#pragma unroll
        for (int j = 0; j < 8; j++) acc[i][j] = 0.0f;

    sgemm_body<512>(g_comb, w_out, acc);

    const int tx = threadIdx.x & 15, ty = threadIdx.x >> 4;
    const int r0 = blockIdx.y * 128 + ty * 8;
    const int c0 = blockIdx.x * 128 + tx * 8;
#pragma unroll
    for (int i = 0; i < 8; i++) {
        const int r = r0 + i;
#pragma unroll
        for (int j = 0; j < 8; j++) {
            const int c = c0 + j;
            float v   = acc[i][j] + b_out[c];
            float at  = tanhf(v);
            float q   = g_comb[(size_t)r * 512 + 256 + c];
            float sgv = g_sg[(size_t)r * 256 + c];
            float ugv = g_ug[(size_t)r * 256 + c];
            float curr = q + sgv * at;
            float h   = hidden[(size_t)r * 256 + c];
            out[(size_t)r * 256 + c] = curr + ugv * (h - curr);
        }
    }
}

// ---------------- launch ---------------------------------------------------------
extern "C" void kernel_launch(void* const* d_in, const int* in_sizes, int n_in,
                              void* d_out, int out_size) {
    const float* input_tensor = (const float*)d_in[0];  // (B, 258)
    const float* hidden       = (const float*)d_in[1];  // (B, 256)
    const float* w_ih         = (const float*)d_in[2];  // (1024, 256)
    const float* b_ih         = (const float*)d_in[3];  // (1024)
    const float* w_hh         = (const float*)d_in[4];  // (1024, 256)
    const float* b_hh         = (const float*)d_in[5];  // (1024)
    const float* w_out        = (const float*)d_in[6];  // (256, 512)
    const float* b_out        = (const float*)d_in[7];  // (256)
    const float* memory       = (const float*)d_in[8];  // (70, 70, 256)
    float* out = (float*)d_out;                         // (B, 256)

    pack_kernel<<<8192, 256>>>(input_tensor);
    gemm1_kernel<<<dim3(8, 128, 2), 256>>>(hidden, w_ih, b_ih, w_hh, b_hh);
    phaseB_kernel<<<BSZ, 256>>>(input_tensor, memory);
    gemm2_kernel<<<dim3(2, 128), 256>>>(w_out, b_out, hidden, out);
}

// round 3
// speedup vs baseline: 1.4951x; 1.4951x over previous
#include <cuda_runtime.h>
#include <cuda_bf16.h>
#include <math.h>
#include <stdint.h>

// Problem constants
#define BSZ  16384
#define HD   256
#define GXD  70
#define GYD  70
#define SWIN 2
#define NKW  25   // 5x5 window

// ---------------- scratch (static device memory, no allocations) ----------------
// bf16 split-extended operands: A-side layout [hi | hi | lo], W-side [hi | lo | hi]
__device__ __align__(16) __nv_bfloat16 g_Aext[(size_t)BSZ * 768];
__device__ __align__(16) __nv_bfloat16 g_Hext[(size_t)BSZ * 768];
__device__ __align__(16) __nv_bfloat16 g_Wih [(size_t)1024 * 768];
__device__ __align__(16) __nv_bfloat16 g_Whh [(size_t)1024 * 768];
__device__ __align__(16) __nv_bfloat16 g_Wout[(size_t)256 * 1536];
__device__ __align__(16) __nv_bfloat16 g_Cext[(size_t)BSZ * 1536];
__device__ float g_gi[(size_t)BSZ * 1024];
__device__ float g_gh[(size_t)BSZ * 1024];
__device__ float g_sg[(size_t)BSZ * 256];
__device__ float g_ug[(size_t)BSZ * 256];

__device__ __forceinline__ float sigmoidf_(float x) {
    return 1.0f / (1.0f + expf(-x));
}

__device__ __forceinline__ uint32_t smem_u32(const void* p) {
    uint32_t a;
    asm("{ .reg .u64 t; cvta.to.shared.u64 t, %1; cvt.u32.u64 %0, t; }" : "=r"(a) : "l"(p));
    return a;
}

__device__ __forceinline__ void ldsm_x4(uint32_t addr, uint32_t& r0, uint32_t& r1,
                                        uint32_t& r2, uint32_t& r3) {
    asm volatile("ldmatrix.sync.aligned.m8n8.x4.shared.b16 {%0,%1,%2,%3}, [%4];"
                 : "=r"(r0), "=r"(r1), "=r"(r2), "=r"(r3) : "r"(addr));
}

__device__ __forceinline__ void mma16816(float& d0, float& d1, float& d2, float& d3,
                                         uint32_t a0, uint32_t a1, uint32_t a2, uint32_t a3,
                                         uint32_t b0, uint32_t b1) {
    asm volatile("mma.sync.aligned.m16n8k16.row.col.f32.bf16.bf16.f32 "
                 "{%0,%1,%2,%3}, {%4,%5,%6,%7}, {%8,%9}, {%0,%1,%2,%3};"
                 : "+f"(d0), "+f"(d1), "+f"(d2), "+f"(d3)
                 : "r"(a0), "r"(a1), "r"(a2), "r"(a3), "r"(b0), "r"(b1));
}

// SMEM tile: 128 rows x 64 bf16, row padded 128B -> 144B (conflict-free)
#define ROWB 144
#define TILE_SMEM (128 * ROWB)

// ---------------- conversion kernels (fp32 -> split bf16, extended K) ----------
// A-side layout per row: [hi(K) | hi(K) | lo(K)]
__global__ __launch_bounds__(256) void conv_ah_kernel(const float* __restrict__ input_tensor,
                                                      const float* __restrict__ hidden) {
    size_t i = (size_t)blockIdx.x * 256 + threadIdx.x;   // BSZ*128 threads, 2 cols each
    size_t b = i >> 7;
    int c = (int)(i & 127) * 2;
    const float* src; __nv_bfloat16* dst; int stride;
    if (blockIdx.z == 0) { src = input_tensor; dst = g_Aext; stride = 258; }
    else                 { src = hidden;       dst = g_Hext; stride = 256; }
    float2 v = *(const float2*)(src + b * stride + c);
    __nv_bfloat16 h0 = __float2bfloat16(v.x);
    __nv_bfloat16 h1 = __float2bfloat16(v.y);
    __nv_bfloat16 l0 = __float2bfloat16(v.x - __bfloat162float(h0));
    __nv_bfloat16 l1 = __float2bfloat16(v.y - __bfloat162float(h1));
    __nv_bfloat162 hh; hh.x = h0; hh.y = h1;
    __nv_bfloat162 ll; ll.x = l0; ll.y = l1;
    __nv_bfloat16* d = dst + b * 768 + c;
    *(__nv_bfloat162*)(d)       = hh;
    *(__nv_bfloat162*)(d + 256) = hh;
    *(__nv_bfloat162*)(d + 512) = ll;
}

// W-side layout per row: [hi(K) | lo(K) | hi(K)]
__global__ __launch_bounds__(256) void conv_w_kernel(const float* __restrict__ src,
                                                     int sel, int K) {
    __nv_bfloat16* dst = (sel == 0) ? g_Wih : (sel == 1) ? g_Whh : g_Wout;
    size_t e = ((size_t)blockIdx.x * 256 + threadIdx.x) * 2;
    size_t r = e / (size_t)K;
    int k = (int)(e % (size_t)K);
    float2 v = *(const float2*)(src + r * K + k);
    __nv_bfloat16 h0 = __float2bfloat16(v.x);
    __nv_bfloat16 h1 = __float2bfloat16(v.y);
    __nv_bfloat16 l0 = __float2bfloat16(v.x - __bfloat162float(h0));
    __nv_bfloat16 l1 = __float2bfloat16(v.y - __bfloat162float(h1));
    __nv_bfloat162 hh; hh.x = h0; hh.y = h1;
    __nv_bfloat162 ll; ll.x = l0; ll.y = l1;
    __nv_bfloat16* d = dst + r * (size_t)(3 * K) + k;
    *(__nv_bfloat162*)(d)         = hh;
    *(__nv_bfloat162*)(d + K)     = ll;
    *(__nv_bfloat162*)(d + 2 * K) = hh;
}

// ---------------- mma.sync GEMM mainloop ---------------------------------------
// acc[mt][nt][4]: warp tile 32(m) x 64(n); 8 warps in 4(m) x 2(n).
template <int KEXT>
__device__ __forceinline__ void mma_gemm_main(const __nv_bfloat16* __restrict__ A,
                                              const __nv_bfloat16* __restrict__ W,
                                              __nv_bfloat16* sA, __nv_bfloat16* sB,
                                              float (&acc)[2][8][4]) {
    const int tid = threadIdx.x;
    const int wid = tid >> 5, lane = tid & 31;
    const int wm = (wid & 3) * 32;
    const int wn = (wid >> 2) * 64;

    // global load mapping: row = tid>>1 (0..127), seg = tid&1 (32 bf16 each)
    const int grow = tid >> 1, gseg = tid & 1;
    const __nv_bfloat16* ga = A + (size_t)(blockIdx.y * 128 + grow) * KEXT + gseg * 32;
    const __nv_bfloat16* gw = W + (size_t)(blockIdx.x * 128 + grow) * KEXT + gseg * 32;
    char* stA = (char*)sA + grow * ROWB + gseg * 64;
    char* stB = (char*)sB + grow * ROWB + gseg * 64;

    // ldmatrix lane address bases (byte offsets within tile)
    const uint32_t aBase = smem_u32(sA), bBase = smem_u32(sB);
    uint32_t a_off[2], b_off[4];
#pragma unroll
    for (int mt = 0; mt < 2; mt++)
        a_off[mt] = aBase + (uint32_t)(wm + mt * 16 + (lane & 8) + (lane & 7)) * ROWB
                  + ((lane >> 4) * 16);
#pragma unroll
    for (int nt2 = 0; nt2 < 4; nt2++)
        b_off[nt2] = bBase + (uint32_t)(wn + nt2 * 16 + ((lane >> 4) & 1) * 8 + (lane & 7)) * ROWB
                   + (((lane >> 3) & 1) * 16);

    constexpr int NC = KEXT / 64;
#pragma unroll 1
    for (int ch = 0; ch < NC; ch++) {
        __syncthreads();
#pragma unroll
        for (int j = 0; j < 4; j++) {
            *(uint4*)(stA + j * 16) = *(const uint4*)(ga + ch * 64 + j * 8);
            *(uint4*)(stB + j * 16) = *(const uint4*)(gw + ch * 64 + j * 8);
        }
        __syncthreads();
#pragma unroll
        for (int ks = 0; ks < 4; ks++) {
            const uint32_t kb = ks * 32;
            uint32_t a[2][4], b[4][4];
#pragma unroll
            for (int mt = 0; mt < 2; mt++)
                ldsm_x4(a_off[mt] + kb, a[mt][0], a[mt][1], a[mt][2], a[mt][3]);
#pragma unroll
            for (int nt2 = 0; nt2 < 4; nt2++)
                ldsm_x4(b_off[nt2] + kb, b[nt2][0], b[nt2][1], b[nt2][2], b[nt2][3]);
#pragma unroll
            for (int mt = 0; mt < 2; mt++)
#pragma unroll
                for (int nt = 0; nt < 8; nt++) {
                    const uint32_t b0 = b[nt >> 1][(nt & 1) * 2 + 0];
                    const uint32_t b1 = b[nt >> 1][(nt & 1) * 2 + 1];
                    mma16816(acc[mt][nt][0], acc[mt][nt][1], acc[mt][nt][2], acc[mt][nt][3],
                             a[mt][0], a[mt][1], a[mt][2], a[mt][3], b0, b1);
                }
        }
    }
}

// ---------------- kernel: gi / gh GEMMs (z=0: feature, z=1: hidden) -------------
__global__ __launch_bounds__(256) void tgemm1_kernel(const float* __restrict__ b_ih,
                                                     const float* __restrict__ b_hh) {
    __shared__ __nv_bfloat16 sA[TILE_SMEM / 2];
    __shared__ __nv_bfloat16 sB[TILE_SMEM / 2];
    const __nv_bfloat16* A = blockIdx.z ? g_Hext : g_Aext;
    const __nv_bfloat16* W = blockIdx.z ? g_Whh  : g_Wih;
    const float* bias      = blockIdx.z ? b_hh   : b_ih;
    float* C               = blockIdx.z ? g_gh   : g_gi;

    float acc[2][8][4];
#pragma unroll
    for (int mt = 0; mt < 2; mt++)
#pragma unroll
        for (int nt = 0; nt < 8; nt++)
#pragma unroll
            for (int e = 0; e < 4; e++) acc[mt][nt][e] = 0.0f;

    mma_gemm_main<768>(A, W, sA, sB, acc);

    const int wid = threadIdx.x >> 5, lane = threadIdx.x & 31;
    const int wm = (wid & 3) * 32, wn = (wid >> 2) * 64;
    const int gid = lane >> 2, tig = lane & 3;
#pragma unroll
    for (int mt = 0; mt < 2; mt++) {
        const int r = blockIdx.y * 128 + wm + mt * 16 + gid;
#pragma unroll
        for (int nt = 0; nt < 8; nt++) {
            const int c = blockIdx.x * 128 + wn + nt * 8 + 2 * tig;
            float2 bv = *(const float2*)(bias + c);
            float2 v0 = { acc[mt][nt][0] + bv.x, acc[mt][nt][1] + bv.y };
            float2 v1 = { acc[mt][nt][2] + bv.x, acc[mt][nt][3] + bv.y };
            *(float2*)(C + (size_t)r * 1024 + c)       = v0;
            *(float2*)(C + (size_t)(r + 8) * 1024 + c) = v1;
        }
    }
}

// ---------------- kernel: gates + attention over 5x5 context ------------------
__global__ __launch_bounds__(256) void phaseB_kernel(
    const float* __restrict__ input_tensor,
    const float* __restrict__ memory) {
    const int b = blockIdx.x;
    const int t = threadIdx.x;

    __shared__ float q_s[HD];
    __shared__ float ctx[NKW][HD];
    __shared__ float attn_s[NKW];
    __shared__ float w_s[NKW];

    const float* gi = g_gi + (size_t)b * 1024;
    const float* gh = g_gh + (size_t)b * 1024;
    float i_r = gi[t],       h_r = gh[t];
    float i_i = gi[256 + t], h_i = gh[256 + t];
    float i_n = gi[512 + t], h_n = gh[512 + t];
    float i_s = gi[768 + t], h_s = gh[768 + t];

    float rg = sigmoidf_(i_r + h_r);
    float ug = sigmoidf_(i_i + h_i);
    float sg = sigmoidf_(i_s + h_s);
    float q  = tanhf(i_n + rg * h_n);
    q_s[t] = q;
    g_sg[(size_t)b * HD + t] = sg;
    g_ug[(size_t)b * HD + t] = ug;

    int gx = (int)input_tensor[(size_t)b * 258 + 256] + SWIN;
    int gy = (int)input_tensor[(size_t)b * 258 + 257] + SWIN;
    gx = min(max(gx, 0), GXD - 1);
    gy = min(max(gy, 0), GYD - 1);

#pragma unroll
    for (int k = 0; k < NKW; k++) {
        int xi = min(max(gx + k / 5 - SWIN, 0), GXD - 1);
        int yi = min(max(gy + k % 5 - SWIN, 0), GYD - 1);
        ctx[k][t] = __ldg(&memory[((size_t)xi * GYD + yi) * HD + t]);
    }
    __syncthreads();

    const int lane = t & 31, wrp = t >> 5;
    for (int k = wrp; k < NKW; k += 8) {
        float sum = 0.0f;
#pragma unroll
        for (int e = 0; e < 8; e++)
            sum += q_s[lane + e * 32] * ctx[k][lane + e * 32];
#pragma unroll
        for (int off = 16; off; off >>= 1)
            sum += __shfl_xor_sync(0xffffffffu, sum, off);
        if (lane == 0) attn_s[k] = sum;
    }
    __syncthreads();

    if (t < 32) {
        float v = (lane < NKW) ? attn_s[lane] : -INFINITY;
        if (v == 0.0f) v = -INFINITY;
        float mx = v;
#pragma unroll
        for (int off = 16; off; off >>= 1)
            mx = fmaxf(mx, __shfl_xor_sync(0xffffffffu, mx, off));
        float e = (mx == -INFINITY) ? 0.0f : expf(v - mx);
        float den = e;
#pragma unroll
        for (int off = 16; off; off >>= 1)
            den += __shfl_xor_sync(0xffffffffu, den, off);
        float wv = (den > 0.0f) ? (e / den) : 0.0f;
        if (lane < NKW) w_s[lane] = wv;
    }
    __syncthreads();

    float mix = 0.0f;
#pragma unroll
    for (int k = 0; k < NKW; k++)
        mix = fmaf(w_s[k], ctx[k][t], mix);

    // write combined = [mix | q] directly as split-extended bf16 (A-side layout)
    __nv_bfloat16 mh = __float2bfloat16(mix);
    __nv_bfloat16 ml = __float2bfloat16(mix - __bfloat162float(mh));
    __nv_bfloat16 qh = __float2bfloat16(q);
    __nv_bfloat16 ql = __float2bfloat16(q - __bfloat162float(qh));
    __nv_bfloat16* crow = g_Cext + (size_t)b * 1536;
    crow[t]          = mh;
    crow[512 + t]    = mh;
    crow[1024 + t]   = ml;
    crow[256 + t]    = qh;
    crow[768 + t]    = qh;
    crow[1280 + t]   = ql;
}

// ---------------- kernel: output GEMM + fused GRU epilogue ----------------------
__global__ __launch_bounds__(256) void tgemm2_kernel(const float* __restrict__ b_out,
                                                     const float* __restrict__ hidden,
                                                     float* __restrict__ out) {
    __shared__ __nv_bfloat16 sA[TILE_SMEM / 2];
    __shared__ __nv_bfloat16 sB[TILE_SMEM / 2];

    float acc[2][8][4];
#pragma unroll
    for (int mt = 0; mt < 2; mt++)
#pragma unroll
        for (int nt = 0; nt < 8; nt++)
#pragma unroll
            for (int e = 0; e < 4; e++) acc[mt][nt][e] = 0.0f;

    mma_gemm_main<1536>(g_Cext, g_Wout, sA, sB, acc);

    const int wid = threadIdx.x >> 5, lane = threadIdx.x & 31;
    const int wm = (wid & 3) * 32, wn = (wid >> 2) * 64;
    const int gid = lane >> 2, tig = lane & 3;
#pragma unroll
    for (int mt = 0; mt < 2; mt++) {
        const int rbase = blockIdx.y * 128 + wm + mt * 16 + gid;
#pragma unroll
        for (int nt = 0; nt < 8; nt++) {
            const int c = blockIdx.x * 128 + wn + nt * 8 + 2 * tig;
            float2 bv = *(const float2*)(b_out + c);
#pragma unroll
            for (int half = 0; half < 2; half++) {
                const int r = rbase + half * 8;
                const __nv_bfloat16* crow = g_Cext + (size_t)r * 1536;
                __nv_bfloat162 qh2 = *(const __nv_bfloat162*)(crow + 256 + c);
                __nv_bfloat162 ql2 = *(const __nv_bfloat162*)(crow + 1280 + c);
                float2 sg2 = *(const float2*)(g_sg + (size_t)r * 256 + c);
                float2 ug2 = *(const float2*)(g_ug + (size_t)r * 256 + c);
                float2 h2  = *(const float2*)(hidden + (size_t)r * 256 + c);
                float q0 = __bfloat162float(qh2.x) + __bfloat162float(ql2.x);
                float q1 = __bfloat162float(qh2.y) + __bfloat162float(ql2.y);
                float v0 = acc[mt][nt][half * 2 + 0] + bv.x;
                float v1 = acc[mt][nt][half * 2 + 1] + bv.y;
                float a0 = tanhf(v0), a1 = tanhf(v1);
                float cu0 = q0 + sg2.x * a0;
                float cu1 = q1 + sg2.y * a1;
                float2 o;
                o.x = cu0 + ug2.x * (h2.x - cu0);
                o.y = cu1 + ug2.y * (h2.y - cu1);
                *(float2*)(out + (size_t)r * 256 + c) = o;
            }
        }
    }
}

// ---------------- launch ---------------------------------------------------------
extern "C" void kernel_launch(void* const* d_in, const int* in_sizes, int n_in,
                              void* d_out, int out_size) {
    const float* input_tensor = (const float*)d_in[0];  // (B, 258)
    const float* hidden       = (const float*)d_in[1];  // (B, 256)
    const float* w_ih         = (const float*)d_in[2];  // (1024, 256)
    const float* b_ih         = (const float*)d_in[3];  // (1024)
    const float* w_hh         = (const float*)d_in[4];  // (1024, 256)
    const float* b_hh         = (const float*)d_in[5];  // (1024)
    const float* w_out        = (const float*)d_in[6];  // (256, 512)
    const float* b_out        = (const float*)d_in[7];  // (256)
    const float* memory       = (const float*)d_in[8];  // (70, 70, 256)
    float* out = (float*)d_out;                         // (B, 256)

    conv_ah_kernel<<<dim3(8192, 1, 2), 256>>>(input_tensor, hidden);
    conv_w_kernel<<<512, 256>>>(w_ih, 0, 256);
    conv_w_kernel<<<512, 256>>>(w_hh, 1, 256);
    conv_w_kernel<<<256, 256>>>(w_out, 2, 512);
    tgemm1_kernel<<<dim3(8, 128, 2), 256>>>(b_ih, b_hh);
    phaseB_kernel<<<BSZ, 256>>>(input_tensor, memory);
    tgemm2_kernel<<<dim3(2, 128), 256>>>(b_out, hidden, out);
}

// round 4
// speedup vs baseline: 2.0619x; 1.3791x over previous
#include <cuda_runtime.h>
#include <cuda_bf16.h>
#include <math.h>
#include <stdint.h>

// Problem constants
#define BSZ  16384
#define HD   256
#define GXD  70
#define GYD  70
#define SWIN 2
#define NKW  25   // 5x5 window

// ---------------- scratch (static device memory, no allocations) ----------------
// bf16 split-extended operands: A-side layout [hi | hi | lo], W-side [hi | lo | hi]
__device__ __align__(16) __nv_bfloat16 g_Aext[(size_t)BSZ * 768];
__device__ __align__(16) __nv_bfloat16 g_Hext[(size_t)BSZ * 768];
__device__ __align__(16) __nv_bfloat16 g_Wih [(size_t)1024 * 768];
__device__ __align__(16) __nv_bfloat16 g_Whh [(size_t)1024 * 768];
__device__ __align__(16) __nv_bfloat16 g_Wout[(size_t)256 * 1536];
__device__ __align__(16) __nv_bfloat16 g_Cext[(size_t)BSZ * 1536];
__device__ float g_gi[(size_t)BSZ * 1024];
__device__ float g_gh[(size_t)BSZ * 1024];
__device__ float g_sg[(size_t)BSZ * 256];
__device__ float g_ug[(size_t)BSZ * 256];

__device__ __forceinline__ float sigmoidf_(float x) {
    return 1.0f / (1.0f + expf(-x));
}

__device__ __forceinline__ uint32_t smem_u32(const void* p) {
    uint32_t a;
    asm("{ .reg .u64 t; cvta.to.shared.u64 t, %1; cvt.u32.u64 %0, t; }" : "=r"(a) : "l"(p));
    return a;
}

__device__ __forceinline__ void ldsm_x4(uint32_t addr, uint32_t& r0, uint32_t& r1,
                                        uint32_t& r2, uint32_t& r3) {
    asm volatile("ldmatrix.sync.aligned.m8n8.x4.shared.b16 {%0,%1,%2,%3}, [%4];"
                 : "=r"(r0), "=r"(r1), "=r"(r2), "=r"(r3) : "r"(addr));
}

__device__ __forceinline__ void mma16816(float& d0, float& d1, float& d2, float& d3,
                                         uint32_t a0, uint32_t a1, uint32_t a2, uint32_t a3,
                                         uint32_t b0, uint32_t b1) {
    asm volatile("mma.sync.aligned.m16n8k16.row.col.f32.bf16.bf16.f32 "
                 "{%0,%1,%2,%3}, {%4,%5,%6,%7}, {%8,%9}, {%0,%1,%2,%3};"
                 : "+f"(d0), "+f"(d1), "+f"(d2), "+f"(d3)
                 : "r"(a0), "r"(a1), "r"(a2), "r"(a3), "r"(b0), "r"(b1));
}

#define CP_ASYNC16(dst, src) \
    asm volatile("cp.async.cg.shared.global [%0], [%1], 16;" :: "r"(dst), "l"(src))
#define CP_COMMIT() asm volatile("cp.async.commit_group;")
#define CP_WAIT2()  asm volatile("cp.async.wait_group 2;")

// Swizzled tile: 128 rows x 128B (64 bf16), unit' = unit ^ (row&7). 16KB/tile.
#define TILEB   16384
#define STAGEB  32768   // A tile + B tile
#define NSTAGE  3
#define SMEM_BYTES (NSTAGE * STAGEB)

// ---------------- conversion kernels (fp32 -> split bf16, extended K) ----------
// A-side layout per row: [hi(K) | hi(K) | lo(K)]
__global__ __launch_bounds__(256) void conv_ah_kernel(const float* __restrict__ input_tensor,
                                                      const float* __restrict__ hidden) {
    size_t i = (size_t)blockIdx.x * 256 + threadIdx.x;   // BSZ*128 threads, 2 cols each
    size_t b = i >> 7;
    int c = (int)(i & 127) * 2;
    const float* src; __nv_bfloat16* dst; int stride;
    if (blockIdx.z == 0) { src = input_tensor; dst = g_Aext; stride = 258; }
    else                 { src = hidden;       dst = g_Hext; stride = 256; }
    float2 v = *(const float2*)(src + b * stride + c);
    __nv_bfloat16 h0 = __float2bfloat16(v.x);
    __nv_bfloat16 h1 = __float2bfloat16(v.y);
    __nv_bfloat16 l0 = __float2bfloat16(v.x - __bfloat162float(h0));
    __nv_bfloat16 l1 = __float2bfloat16(v.y - __bfloat162float(h1));
    __nv_bfloat162 hh; hh.x = h0; hh.y = h1;
    __nv_bfloat162 ll; ll.x = l0; ll.y = l1;
    __nv_bfloat16* d = dst + b * 768 + c;
    *(__nv_bfloat162*)(d)       = hh;
    *(__nv_bfloat162*)(d + 256) = hh;
    *(__nv_bfloat162*)(d + 512) = ll;
}

// W-side layout per row: [hi(K) | lo(K) | hi(K)]; z selects {w_ih, w_hh, w_out}
__global__ __launch_bounds__(256) void conv_w_kernel(const float* __restrict__ w_ih,
                                                     const float* __restrict__ w_hh,
                                                     const float* __restrict__ w_out) {
    const int sel = blockIdx.z;
    const float* src = (sel == 0) ? w_ih : (sel == 1) ? w_hh : w_out;
    __nv_bfloat16* dst = (sel == 0) ? g_Wih : (sel == 1) ? g_Whh : g_Wout;
    const int K = (sel == 2) ? 512 : 256;
    const int nblk = (sel == 2) ? 256 : 512;
    if (blockIdx.x >= nblk) return;
    size_t e = ((size_t)blockIdx.x * 256 + threadIdx.x) * 2;
    size_t r = e / (size_t)K;
    int k = (int)(e % (size_t)K);
    float2 v = *(const float2*)(src + r * K + k);
    __nv_bfloat16 h0 = __float2bfloat16(v.x);
    __nv_bfloat16 h1 = __float2bfloat16(v.y);
    __nv_bfloat16 l0 = __float2bfloat16(v.x - __bfloat162float(h0));
    __nv_bfloat16 l1 = __float2bfloat16(v.y - __bfloat162float(h1));
    __nv_bfloat162 hh; hh.x = h0; hh.y = h1;
    __nv_bfloat162 ll; ll.x = l0; ll.y = l1;
    __nv_bfloat16* d = dst + r * (size_t)(3 * K) + k;
    *(__nv_bfloat162*)(d)         = hh;
    *(__nv_bfloat162*)(d + K)     = ll;
    *(__nv_bfloat162*)(d + 2 * K) = hh;
}

// ---------------- pipelined mma.sync GEMM mainloop ------------------------------
// acc[mt][nt][4]: warp tile 32(m) x 64(n); 8 warps in 4(m) x 2(n).
template <int KEXT>
__device__ __forceinline__ void mma_gemm_main(const __nv_bfloat16* __restrict__ A,
                                              const __nv_bfloat16* __restrict__ W,
                                              char* smem, float (&acc)[2][8][4]) {
    const int tid = threadIdx.x;
    const int wid = tid >> 5, lane = tid & 31;
    const int wm = (wid & 3) * 32;
    const int wn = (wid >> 2) * 64;
    const uint32_t sbase = smem_u32(smem);

    // copy mapping: thread handles unit (tid&7), rows (tid>>3)+j*32
    const int crow0 = tid >> 3, cunit = tid & 7;
    const __nv_bfloat16* ga = A + (size_t)(blockIdx.y * 128) * KEXT + cunit * 8;
    const __nv_bfloat16* gw = W + (size_t)(blockIdx.x * 128) * KEXT + cunit * 8;

    // ldmatrix row indices (fixed per fragment slot)
    int rowA[2], rowB[4];
#pragma unroll
    for (int mt = 0; mt < 2; mt++)
        rowA[mt] = wm + mt * 16 + (lane & 8) + (lane & 7);
#pragma unroll
    for (int nt2 = 0; nt2 < 4; nt2++)
        rowB[nt2] = wn + nt2 * 16 + ((lane >> 4) & 1) * 8 + (lane & 7);
    const int uA = lane >> 4;          // 0..1
    const int uB = (lane >> 3) & 1;    // 0..1

    constexpr int NC = KEXT / 64;

    auto issue = [&](int ch) {
        const int s = ch % NSTAGE;
        const uint32_t dA = sbase + s * STAGEB;
        const uint32_t dB = dA + TILEB;
#pragma unroll
        for (int j = 0; j < 4; j++) {
            const int row = crow0 + j * 32;
            const uint32_t off = (uint32_t)row * 128 + (uint32_t)((cunit ^ (row & 7)) * 16);
            const size_t gofs = (size_t)row * KEXT + ch * 64;
            CP_ASYNC16(dA + off, ga + gofs);
            CP_ASYNC16(dB + off, gw + gofs);
        }
        CP_COMMIT();
    };

    issue(0);
    issue(1);
#pragma unroll 1
    for (int ch = 0; ch < NC; ch++) {
        if (ch + 2 < NC) issue(ch + 2); else CP_COMMIT();
        CP_WAIT2();
        __syncthreads();
        const int s = ch % NSTAGE;
        const uint32_t aB = sbase + s * STAGEB;
        const uint32_t bB = aB + TILEB;
#pragma unroll
        for (int ks = 0; ks < 4; ks++) {
            uint32_t a[2][4], b[4][4];
#pragma unroll
            for (int mt = 0; mt < 2; mt++) {
                const int u = ks * 2 + uA;
                const uint32_t addr = aB + (uint32_t)rowA[mt] * 128
                                    + (uint32_t)((u ^ (rowA[mt] & 7)) * 16);
                ldsm_x4(addr, a[mt][0], a[mt][1], a[mt][2], a[mt][3]);
            }
#pragma unroll
            for (int nt2 = 0; nt2 < 4; nt2++) {
                const int u = ks * 2 + uB;
                const uint32_t addr = bB + (uint32_t)rowB[nt2] * 128
                                    + (uint32_t)((u ^ (rowB[nt2] & 7)) * 16);
                ldsm_x4(addr, b[nt2][0], b[nt2][1], b[nt2][2], b[nt2][3]);
            }
#pragma unroll
            for (int mt = 0; mt < 2; mt++)
#pragma unroll
                for (int nt = 0; nt < 8; nt++) {
                    const uint32_t b0 = b[nt >> 1][(nt & 1) * 2 + 0];
                    const uint32_t b1 = b[nt >> 1][(nt & 1) * 2 + 1];
                    mma16816(acc[mt][nt][0], acc[mt][nt][1], acc[mt][nt][2], acc[mt][nt][3],
                             a[mt][0], a[mt][1], a[mt][2], a[mt][3], b0, b1);
                }
        }
        __syncthreads();
    }
}

// ---------------- kernel: gi / gh GEMMs (z=0: feature, z=1: hidden) -------------
__global__ __launch_bounds__(256) void tgemm1_kernel(const float* __restrict__ b_ih,
                                                     const float* __restrict__ b_hh) {
    extern __shared__ char smem[];
    const __nv_bfloat16* A = blockIdx.z ? g_Hext : g_Aext;
    const __nv_bfloat16* W = blockIdx.z ? g_Whh  : g_Wih;
    const float* bias      = blockIdx.z ? b_hh   : b_ih;
    float* C               = blockIdx.z ? g_gh   : g_gi;

    float acc[2][8][4];
#pragma unroll
    for (int mt = 0; mt < 2; mt++)
#pragma unroll
        for (int nt = 0; nt < 8; nt++)
#pragma unroll
            for (int e = 0; e < 4; e++) acc[mt][nt][e] = 0.0f;

    mma_gemm_main<768>(A, W, smem, acc);

    const int wid = threadIdx.x >> 5, lane = threadIdx.x & 31;
    const int wm = (wid & 3) * 32, wn = (wid >> 2) * 64;
    const int gid = lane >> 2, tig = lane & 3;
#pragma unroll
    for (int mt = 0; mt < 2; mt++) {
        const int r = blockIdx.y * 128 + wm + mt * 16 + gid;
#pragma unroll
        for (int nt = 0; nt < 8; nt++) {
            const int c = blockIdx.x * 128 + wn + nt * 8 + 2 * tig;
            float2 bv = *(const float2*)(bias + c);
            float2 v0 = { acc[mt][nt][0] + bv.x, acc[mt][nt][1] + bv.y };
            float2 v1 = { acc[mt][nt][2] + bv.x, acc[mt][nt][3] + bv.y };
            *(float2*)(C + (size_t)r * 1024 + c)       = v0;
            *(float2*)(C + (size_t)(r + 8) * 1024 + c) = v1;
        }
    }
}

// ---------------- kernel: gates + attention over 5x5 context ------------------
__global__ __launch_bounds__(256) void phaseB_kernel(
    const float* __restrict__ input_tensor,
    const float* __restrict__ memory) {
    const int b = blockIdx.x;
    const int t = threadIdx.x;

    __shared__ float q_s[HD];
    __shared__ float ctx[NKW][HD];
    __shared__ float attn_s[NKW];
    __shared__ float w_s[NKW];

    const float* gi = g_gi + (size_t)b * 1024;
    const float* gh = g_gh + (size_t)b * 1024;
    float i_r = gi[t],       h_r = gh[t];
    float i_i = gi[256 + t], h_i = gh[256 + t];
    float i_n = gi[512 + t], h_n = gh[512 + t];
    float i_s = gi[768 + t], h_s = gh[768 + t];

    float rg = sigmoidf_(i_r + h_r);
    float ug = sigmoidf_(i_i + h_i);
    float sg = sigmoidf_(i_s + h_s);
    float q  = tanhf(i_n + rg * h_n);
    q_s[t] = q;
    g_sg[(size_t)b * HD + t] = sg;
    g_ug[(size_t)b * HD + t] = ug;

    int gx = (int)input_tensor[(size_t)b * 258 + 256] + SWIN;
    int gy = (int)input_tensor[(size_t)b * 258 + 257] + SWIN;
    gx = min(max(gx, 0), GXD - 1);
    gy = min(max(gy, 0), GYD - 1);

#pragma unroll
    for (int k = 0; k < NKW; k++) {
        int xi = min(max(gx + k / 5 - SWIN, 0), GXD - 1);
        int yi = min(max(gy + k % 5 - SWIN, 0), GYD - 1);
        ctx[k][t] = __ldg(&memory[((size_t)xi * GYD + yi) * HD + t]);
    }
    __syncthreads();

    const int lane = t & 31, wrp = t >> 5;
    for (int k = wrp; k < NKW; k += 8) {
        float sum = 0.0f;
#pragma unroll
        for (int e = 0; e < 8; e++)
            sum += q_s[lane + e * 32] * ctx[k][lane + e * 32];
#pragma unroll
        for (int off = 16; off; off >>= 1)
            sum += __shfl_xor_sync(0xffffffffu, sum, off);
        if (lane == 0) attn_s[k] = sum;
    }
    __syncthreads();

    if (t < 32) {
        float v = (lane < NKW) ? attn_s[lane] : -INFINITY;
        if (v == 0.0f) v = -INFINITY;
        float mx = v;
#pragma unroll
        for (int off = 16; off; off >>= 1)
            mx = fmaxf(mx, __shfl_xor_sync(0xffffffffu, mx, off));
        float e = (mx == -INFINITY) ? 0.0f : expf(v - mx);
        float den = e;
#pragma unroll
        for (int off = 16; off; off >>= 1)
            den += __shfl_xor_sync(0xffffffffu, den, off);
        float wv = (den > 0.0f) ? (e / den) : 0.0f;
        if (lane < NKW) w_s[lane] = wv;
    }
    __syncthreads();

    float mix = 0.0f;
#pragma unroll
    for (int k = 0; k < NKW; k++)
        mix = fmaf(w_s[k], ctx[k][t], mix);

    // write combined = [mix | q] directly as split-extended bf16 (A-side layout)
    __nv_bfloat16 mh = __float2bfloat16(mix);
    __nv_bfloat16 ml = __float2bfloat16(mix - __bfloat162float(mh));
    __nv_bfloat16 qh = __float2bfloat16(q);
    __nv_bfloat16 ql = __float2bfloat16(q - __bfloat162float(qh));
    __nv_bfloat16* crow = g_Cext + (size_t)b * 1536;
    crow[t]          = mh;
    crow[512 + t]    = mh;
    crow[1024 + t]   = ml;
    crow[256 + t]    = qh;
    crow[768 + t]    = qh;
    crow[1280 + t]   = ql;
}

// ---------------- kernel: output GEMM + fused GRU epilogue ----------------------
__global__ __launch_bounds__(256) void tgemm2_kernel(const float* __restrict__ b_out,
                                                     const float* __restrict__ hidden,
                                                     float* __restrict__ out) {
    extern __shared__ char smem[];

    float acc[2][8][4];
#pragma unroll
    for (int mt = 0; mt < 2; mt++)
#pragma unroll
        for (int nt = 0; nt < 8; nt++)
#pragma unroll
            for (int e = 0; e < 4; e++) acc[mt][nt][e] = 0.0f;

    mma_gemm_main<1536>(g_Cext, g_Wout, smem, acc);

    const int wid = threadIdx.x >> 5, lane = threadIdx.x & 31;
    const int wm = (wid & 3) * 32, wn = (wid >> 2) * 64;
    const int gid = lane >> 2, tig = lane & 3;
#pragma unroll
    for (int mt = 0; mt < 2; mt++) {
        const int rbase = blockIdx.y * 128 + wm + mt * 16 + gid;
#pragma unroll
        for (int nt = 0; nt < 8; nt++) {
            const int c = blockIdx.x * 128 + wn + nt * 8 + 2 * tig;
            float2 bv = *(const float2*)(b_out + c);
#pragma unroll
            for (int half = 0; half < 2; half++) {
                const int r = rbase + half * 8;
                const __nv_bfloat16* crow = g_Cext + (size_t)r * 1536;
                __nv_bfloat162 qh2 = *(const __nv_bfloat162*)(crow + 256 + c);
                __nv_bfloat162 ql2 = *(const __nv_bfloat162*)(crow + 1280 + c);
                float2 sg2 = *(const float2*)(g_sg + (size_t)r * 256 + c);
                float2 ug2 = *(const float2*)(g_ug + (size_t)r * 256 + c);
                float2 h2  = *(const float2*)(hidden + (size_t)r * 256 + c);
                float q0 = __bfloat162float(qh2.x) + __bfloat162float(ql2.x);
                float q1 = __bfloat162float(qh2.y) + __bfloat162float(ql2.y);
                float v0 = acc[mt][nt][half * 2 + 0] + bv.x;
                float v1 = acc[mt][nt][half * 2 + 1] + bv.y;
                float a0 = tanhf(v0), a1 = tanhf(v1);
                float cu0 = q0 + sg2.x * a0;
                float cu1 = q1 + sg2.y * a1;
                float2 o;
                o.x = cu0 + ug2.x * (h2.x - cu0);
                o.y = cu1 + ug2.y * (h2.y - cu1);
                *(float2*)(out + (size_t)r * 256 + c) = o;
            }
        }
    }
}

// ---------------- launch ---------------------------------------------------------
extern "C" void kernel_launch(void* const* d_in, const int* in_sizes, int n_in,
                              void* d_out, int out_size) {
    const float* input_tensor = (const float*)d_in[0];  // (B, 258)
    const float* hidden       = (const float*)d_in[1];  // (B, 256)
    const float* w_ih         = (const float*)d_in[2];  // (1024, 256)
    const float* b_ih         = (const float*)d_in[3];  // (1024)
    const float* w_hh         = (const float*)d_in[4];  // (1024, 256)
    const float* b_hh         = (const float*)d_in[5];  // (1024)
    const float* w_out        = (const float*)d_in[6];  // (256, 512)
    const float* b_out        = (const float*)d_in[7];  // (256)
    const float* memory       = (const float*)d_in[8];  // (70, 70, 256)
    float* out = (float*)d_out;                         // (B, 256)

    // Host-side, idempotent, not a stream op (capture-safe).
    cudaFuncSetAttribute(tgemm1_kernel, cudaFuncAttributeMaxDynamicSharedMemorySize, SMEM_BYTES);
    cudaFuncSetAttribute(tgemm2_kernel, cudaFuncAttributeMaxDynamicSharedMemorySize, SMEM_BYTES);

    conv_ah_kernel<<<dim3(8192, 1, 2), 256>>>(input_tensor, hidden);
    conv_w_kernel<<<dim3(512, 1, 3), 256>>>(w_ih, w_hh, w_out);
    tgemm1_kernel<<<dim3(8, 128, 2), 256, SMEM_BYTES>>>(b_ih, b_hh);
    phaseB_kernel<<<BSZ, 256>>>(input_tensor, memory);
    tgemm2_kernel<<<dim3(2, 128), 256, SMEM_BYTES>>>(b_out, hidden, out);
}